// round 14
// baseline (speedup 1.0000x reference)
#include <cuda_runtime.h>

// KAN layer as dense GEMM, 2 launches.
//   kan_prep : block-partitioned single launch
//              - feature blocks: coalesced input tile load -> smem transpose
//                -> dense 9-vector features (4 nonzero cubic B-spline weights
//                + silu) -> 128B-coalesced stores to Ft[k][b]
//              - c2t blocks: C2t[k][o] = mask*scale_sp*coef | mask*scale_base
//   kan_gemm : M=2048,N=64,K=576 split-K x9; 32b x 64o tile, 128 thr,
//              4b x 4o register tile with packed f32x2 FMAs (8 FFMA2/k);
//              split-K reduce fused into epilogue (threadfence + counter,
//              fixed ks order -> deterministic).

#define IN_DIM  64
#define OUT_DIM 64
#define KDIM    (IN_DIM * 9)      // 576
#define MAXB    2048
#define KSPLIT  9
#define KCHUNK  (KDIM / KSPLIT)   // 64
#define MTILE   32
#define MAXMT   (MAXB / MTILE)    // 64
#define FB      32                // batch rows per feature block

__device__ __align__(16) float g_Ft[KDIM * MAXB];               // 4.5 MB [k][b]
__device__ __align__(16) float g_C2t[KDIM * OUT_DIM];           // 144 KB [k][o]
__device__ __align__(16) float g_Part[KSPLIT * MAXB * OUT_DIM]; // 4.5 MB
__device__ int g_cnt[MAXMT];                                    // zero-init

typedef unsigned long long ull;

__device__ __forceinline__ void ffma2(ull& d, ull a, ull b) {
    asm("fma.rn.f32x2 %0, %1, %2, %0;" : "+l"(d) : "l"(a), "l"(b));
}
__device__ __forceinline__ ull dup2(float v) {
    ull r;
    asm("mov.b64 %0, {%1, %1};" : "=l"(r) : "f"(v));
    return r;
}

// ---------------- phase 1: features (transposed) + coef matrix --------------
__global__ __launch_bounds__(256)
void kan_prep(const float* __restrict__ inp,
              const float* __restrict__ gridp,
              const float* __restrict__ coefp,
              const float* __restrict__ sbase,
              const float* __restrict__ ssp,
              const float* __restrict__ maskp,
              int batch, int featBlocks)
{
    const int bid = blockIdx.x;
    const int tid = threadIdx.x;

    if (bid < featBlocks) {
        // ---- feature block: 32 batch rows x 64 inputs ----
        __shared__ float xs[FB][IN_DIM + 1];   // padded: column reads c-free
        const int b0 = bid * FB;

        // coalesced tile load (2048 contiguous floats)
        for (int idx = tid; idx < FB * IN_DIM; idx += 256) {
            const int b = idx >> 6;
            const int i = idx & 63;
            const int gb = b0 + b;
            xs[b][i] = (gb < batch) ? inp[gb * IN_DIM + i] : 0.0f;
        }
        __syncthreads();

        const int w    = tid >> 5;   // warp 0..7
        const int lane = tid & 31;   // = b within tile

        #pragma unroll
        for (int r = 0; r < 8; ++r) {
            const int i = w * 8 + r;
            const float x = xs[lane][i];

            const float g0 = __ldg(gridp + i * 6 + 0);
            const float g5 = __ldg(gridp + i * 6 + 5);
            const float h  = (g5 - g0) * 0.2f;
            const float mf = (x - (g0 - 3.0f * h)) * (1.0f / h);

            int mi = (int)floorf(mf);
            const float ok = (mi >= 0 && mi < 11) ? 1.0f : 0.0f;
            mi = max(0, min(10, mi));

            const float u  = mf - (float)mi;
            const float v  = 1.0f - u;
            const float u2 = u * u;
            const float u3 = u2 * u;
            float wg[4];
            wg[0] = ok * (v * v * v * (1.0f / 6.0f));
            wg[3] = ok * (u3 * (1.0f / 6.0f));
            wg[1] = ok * ((2.0f / 3.0f) - u2 + 0.5f * u3);
            wg[2] = ok - wg[0] - wg[1] - wg[3];

            float f[9];
            #pragma unroll
            for (int j = 0; j < 9; ++j) f[j] = 0.0f;
            #pragma unroll
            for (int rr = 0; rr < 4; ++rr) {
                const int j = mi - 3 + rr;
                if (j >= 0 && j < 8) f[j] = wg[rr];
            }
            f[8] = __fdividef(x, 1.0f + __expf(-x));   // silu

            #pragma unroll
            for (int j = 0; j < 9; ++j)                // 128B coalesced
                g_Ft[(i * 9 + j) * MAXB + b0 + lane] = f[j];
        }
    } else {
        // ---- c2t block ----
        const int t = (bid - featBlocks) * 256 + tid;  // = k*64 + o
        if (t < KDIM * OUT_DIM) {
            const int o = t & (OUT_DIM - 1);
            const int k = t >> 6;
            const int i = k / 9;
            const int j = k - i * 9;
            const int s = o * IN_DIM + i;
            const float m = maskp[s];
            g_C2t[t] = (j < 8) ? m * ssp[s] * __ldg(coefp + s * 8 + j)
                               : m * sbase[s];
        }
    }
}

// ---------------- phase 2: split-K GEMM + fused reduce ----------------------
__global__ __launch_bounds__(128)
void kan_gemm(float* __restrict__ out, int batch)
{
    __shared__ __align__(16) float As[32][36];   // [k][b], pad 4 (row 144B)
    __shared__ __align__(16) float Bs[32][64];   // [k][o]
    __shared__ int s_last;

    const int mt = blockIdx.x;        // m-tile
    const int ks = blockIdx.y;        // k-split
    const int b0 = mt * MTILE;
    const int k0 = ks * KCHUNK;

    const int tid = threadIdx.x;
    const int tx = tid & 15;          // o-quad
    const int ty = tid >> 4;          // b-quad (0..7)

    // packed accumulators: acc[o][p], p = b-pair {b0b1, b2b3}
    ull acc[4][2];
    #pragma unroll
    for (int o = 0; o < 4; ++o) { acc[o][0] = 0; acc[o][1] = 0; }

    #pragma unroll 1
    for (int kk = 0; kk < KCHUNK / 32; ++kk) {
        const int kb = k0 + kk * 32;

        // fill A: 32k x 32b = 256 float4, 2 per thread
        #pragma unroll
        for (int p = 0; p < 2; ++p) {
            const int q  = tid + 128 * p;
            const int ka = q >> 3;
            const int bq = (q & 7) * 4;
            *(float4*)&As[ka][bq] =
                *(const float4*)&g_Ft[(kb + ka) * MAXB + b0 + bq];
        }
        // fill B: 32k x 64o -> 4 float4 per thread
        #pragma unroll
        for (int p = 0; p < 4; ++p) {
            const int q   = tid + 128 * p;
            const int kr  = q >> 4;
            const int oq  = (q & 15) * 4;
            *(float4*)&Bs[kr][oq] =
                *(const float4*)&g_C2t[(kb + kr) * OUT_DIM + oq];
        }
        __syncthreads();

        #pragma unroll
        for (int k = 0; k < 32; ++k) {
            // a: two packed b-pairs (bitcast of 16B-aligned float4)
            const ulonglong2 a = *(const ulonglong2*)&As[k][ty * 4];
            const float4 bq = *(const float4*)&Bs[k][tx * 4];
            const ull d0 = dup2(bq.x);
            const ull d1 = dup2(bq.y);
            const ull d2 = dup2(bq.z);
            const ull d3 = dup2(bq.w);
            ffma2(acc[0][0], a.x, d0); ffma2(acc[0][1], a.y, d0);
            ffma2(acc[1][0], a.x, d1); ffma2(acc[1][1], a.y, d1);
            ffma2(acc[2][0], a.x, d2); ffma2(acc[2][1], a.y, d2);
            ffma2(acc[3][0], a.x, d3); ffma2(acc[3][1], a.y, d3);
        }
        __syncthreads();
    }

    // unpack and write partial tile: g_Part[(ks,b)][o quad]
    {
        union { ull u; float2 f; } up;
        float av[4][4];   // [o][ib]
        #pragma unroll
        for (int o = 0; o < 4; ++o) {
            up.u = acc[o][0]; av[o][0] = up.f.x; av[o][1] = up.f.y;
            up.u = acc[o][1]; av[o][2] = up.f.x; av[o][3] = up.f.y;
        }
        #pragma unroll
        for (int ib = 0; ib < 4; ++ib) {
            const int b = b0 + ty * 4 + ib;
            float4 vOut = make_float4(av[0][ib], av[1][ib], av[2][ib], av[3][ib]);
            *(float4*)&g_Part[((ks << 11) + b) * OUT_DIM + tx * 4] = vOut;
        }
    }

    // ---- fused reduce: last of the KSPLIT blocks for this m-tile sums ----
    __threadfence();
    __syncthreads();
    if (tid == 0) {
        const int old = atomicAdd(&g_cnt[mt], 1);
        s_last = (old == KSPLIT - 1) ? 1 : 0;
    }
    __syncthreads();

    if (s_last) {
        __threadfence();
        const int o4 = (tid & 15) * 4;
        const int br = tid >> 4;       // 0..7
        #pragma unroll
        for (int p = 0; p < 4; ++p) {
            const int bl = br + p * 8;
            const int b  = b0 + bl;
            float4 v = make_float4(0.f, 0.f, 0.f, 0.f);
            #pragma unroll
            for (int kk = 0; kk < KSPLIT; ++kk) {
                const float4 q = *(const float4*)
                    &g_Part[((kk << 11) + b) * OUT_DIM + o4];
                v.x += q.x; v.y += q.y; v.z += q.z; v.w += q.w;
            }
            if (b < batch)
                *(float4*)&out[b * OUT_DIM + o4] = v;
        }
        if (tid == 0) g_cnt[mt] = 0;   // self-reset for graph replay
    }
}

extern "C" void kernel_launch(void* const* d_in, const int* in_sizes, int n_in,
                              void* d_out, int out_size)
{
    const float* inp   = (const float*)d_in[0];   // (batch, 64)
    const float* gridp = (const float*)d_in[1];   // (4096, 6)
    const float* coefp = (const float*)d_in[2];   // (4096, 8)
    const float* sbase = (const float*)d_in[3];   // (4096,)
    const float* ssp   = (const float*)d_in[4];   // (4096,)
    const float* maskp = (const float*)d_in[5];   // (4096,)
    float* out = (float*)d_out;                   // (batch, 64)

    int batch = in_sizes[0] / IN_DIM;
    if (batch > MAXB) batch = MAXB;

    const int featBlocks = (batch + FB - 1) / FB;            // 64
    const int c2tBlocks  = (KDIM * OUT_DIM + 255) / 256;     // 144
    kan_prep<<<featBlocks + c2tBlocks, 256>>>(inp, gridp, coefp, sbase, ssp,
                                              maskp, batch, featBlocks);

    const int mtiles = (batch + MTILE - 1) / MTILE;   // 64
    dim3 ggrid(mtiles, KSPLIT);                       // 64 x 9 = 576 blocks
    kan_gemm<<<ggrid, 128>>>(out, batch);
}

// round 15
// speedup vs baseline: 1.1265x; 1.1265x over previous
#include <cuda_runtime.h>

// KAN layer as GEMM with K split BY INPUT GROUPS (8 inputs = 72 k per chunk),
// so each GEMM block computes its own feature sub-tile in smem — no global
// feature array, no prep pass.
//   kan_c2t  : C2t[k][o] = mask*scale_sp*coef (j<8) | mask*scale_base (j=8)
//   kan_gemm : grid (64 m-tiles x 8 k-chunks) x 256 thr  (~44% occ)
//              (a) coalesced 32b x 8i input tile -> smem -> per-thread
//                  feature eval (4 nonzero cubic B-spline wts + silu) into
//                  Fs[72][32+pad]
//              (b) 72-k loop: A = warp-broadcast LDS.128 (4 b packed),
//                  B = conflict-free LDS.64 (2 o), 4 FFMA2 -> 16 MACs
//              (c) split-K reduce fused in epilogue (threadfence+counter,
//                  fixed ks order -> deterministic)

#define IN_DIM  64
#define OUT_DIM 64
#define MAXB    2048
#define KSPLIT  8                 // chunks of 8 inputs
#define IPC     8                 // inputs per chunk
#define KCHUNK  (IPC * 9)         // 72
#define MTILE   32
#define MAXMT   (MAXB / MTILE)    // 64
#define ASTRIDE 36                // Fs row words (144B, 16B-aligned, padded)

__device__ __align__(16) float g_C2t[KSPLIT * KCHUNK * OUT_DIM];   // 144 KB
__device__ __align__(16) float g_Part[KSPLIT * MAXB * OUT_DIM];    // 4 MB
__device__ int g_cnt[MAXMT];                                        // zero-init

typedef unsigned long long ull;

__device__ __forceinline__ void ffma2(ull& d, ull a, ull b) {
    asm("fma.rn.f32x2 %0, %1, %2, %0;" : "+l"(d) : "l"(a), "l"(b));
}
__device__ __forceinline__ ull dup2(float v) {
    ull r;
    asm("mov.b64 %0, {%1, %1};" : "=l"(r) : "f"(v));
    return r;
}

// ---------------- scaled coefficient matrix --------------------------------
__global__ __launch_bounds__(256)
void kan_c2t(const float* __restrict__ coefp,
             const float* __restrict__ sbase,
             const float* __restrict__ ssp,
             const float* __restrict__ maskp)
{
    const int t = blockIdx.x * blockDim.x + threadIdx.x;   // = k*64 + o
    if (t >= KSPLIT * KCHUNK * OUT_DIM) return;
    const int o = t & (OUT_DIM - 1);
    const int k = t >> 6;          // global k = i*9 + j
    const int i = k / 9;
    const int j = k - i * 9;
    const int s = o * IN_DIM + i;
    const float m = maskp[s];
    g_C2t[t] = (j < 8) ? m * ssp[s] * __ldg(coefp + s * 8 + j)
                       : m * sbase[s];
}

// ---------------- fused features + split-K GEMM + reduce --------------------
__global__ __launch_bounds__(256)
void kan_gemm(const float* __restrict__ inp,
              const float* __restrict__ gridp,
              float* __restrict__ out,
              int batch)
{
    __shared__ __align__(16) float Fs[KCHUNK * ASTRIDE];   // 10.1 KB [k][b]
    __shared__ __align__(16) float Bs[KCHUNK * OUT_DIM];   // 18.0 KB [k][o]
    __shared__ float xs[MTILE][IPC + 1];                   // padded transpose
    __shared__ int s_last;

    const int mt = blockIdx.x;     // m-tile
    const int ks = blockIdx.y;     // input-group chunk
    const int b0 = mt * MTILE;
    const int i0 = ks * IPC;
    const int tid = threadIdx.x;

    // ---- input tile load: 32 b x 8 i, coalesced 32B segments ----
    {
        const int b = tid >> 3;          // 0..31
        const int i = tid & 7;           // 0..7
        const int gb = b0 + b;
        xs[b][i] = (gb < batch) ? inp[gb * IN_DIM + i0 + i] : 0.0f;
    }

    // ---- Bs fill: 72x64 floats = 1152 float4 ----
    {
        const float4* src = (const float4*)(g_C2t + ks * KCHUNK * OUT_DIM);
        float4* dst = (float4*)Bs;
        #pragma unroll
        for (int p = 0; p < 5; ++p) {
            const int idx = tid + 256 * p;
            if (idx < (KCHUNK * OUT_DIM) / 4) dst[idx] = src[idx];
        }
    }
    __syncthreads();

    // ---- features: thread = (iloc = warp, bl = lane) ----
    {
        const int iloc = tid >> 5;       // 0..7
        const int bl   = tid & 31;
        const int i    = i0 + iloc;
        const float x  = xs[bl][iloc];

        const float g0 = __ldg(gridp + i * 6 + 0);   // warp-uniform
        const float g5 = __ldg(gridp + i * 6 + 5);
        const float h  = (g5 - g0) * 0.2f;
        const float mf = (x - (g0 - 3.0f * h)) * (1.0f / h);

        int mi = (int)floorf(mf);
        const float ok = (mi >= 0 && mi < 11) ? 1.0f : 0.0f;
        mi = max(0, min(10, mi));

        const float u  = mf - (float)mi;
        const float v  = 1.0f - u;
        const float u2 = u * u;
        const float u3 = u2 * u;
        float wg[4];
        wg[0] = ok * (v * v * v * (1.0f / 6.0f));
        wg[3] = ok * (u3 * (1.0f / 6.0f));
        wg[1] = ok * ((2.0f / 3.0f) - u2 + 0.5f * u3);
        wg[2] = ok - wg[0] - wg[1] - wg[3];

        float f[9];
        #pragma unroll
        for (int j = 0; j < 9; ++j) f[j] = 0.0f;
        #pragma unroll
        for (int r = 0; r < 4; ++r) {
            const int j = mi - 3 + r;
            if (j >= 0 && j < 8) f[j] = wg[r];
        }
        f[8] = __fdividef(x, 1.0f + __expf(-x));     // silu

        #pragma unroll
        for (int j = 0; j < 9; ++j)                  // lane-contiguous: c-free
            Fs[(iloc * 9 + j) * ASTRIDE + bl] = f[j];
    }
    __syncthreads();

    // ---- 72-k mainloop: thread tile 4b x 2o ----
    const int tx = tid & 31;        // o-pair (o0 = tx*2)
    const int ty = tid >> 5;        // b-quad (b = ty*4 ..)

    ull acc[2][2];                  // [o][b-pair]
    acc[0][0] = 0; acc[0][1] = 0; acc[1][0] = 0; acc[1][1] = 0;

    #pragma unroll 8
    for (int k = 0; k < KCHUNK; ++k) {
        const ulonglong2 a = *(const ulonglong2*)&Fs[k * ASTRIDE + ty * 4];
        const float2 bv = *(const float2*)&Bs[k * OUT_DIM + tx * 2];
        const ull d0 = dup2(bv.x);
        const ull d1 = dup2(bv.y);
        ffma2(acc[0][0], a.x, d0); ffma2(acc[0][1], a.y, d0);
        ffma2(acc[1][0], a.x, d1); ffma2(acc[1][1], a.y, d1);
    }

    // ---- write partial tile: float2 {o0,o0+1} per b, lanes -> contiguous ----
    {
        union { ull u; float2 f; } u00, u01, u10, u11;
        u00.u = acc[0][0]; u01.u = acc[0][1];   // o0 : b+0,b+1 / b+2,b+3
        u10.u = acc[1][0]; u11.u = acc[1][1];   // o0+1
        const float vo0[4] = { u00.f.x, u00.f.y, u01.f.x, u01.f.y };
        const float vo1[4] = { u10.f.x, u10.f.y, u11.f.x, u11.f.y };
        #pragma unroll
        for (int ib = 0; ib < 4; ++ib) {
            const int b = b0 + ty * 4 + ib;
            *(float2*)&g_Part[((ks << 11) + b) * OUT_DIM + tx * 2] =
                make_float2(vo0[ib], vo1[ib]);
        }
    }

    // ---- fused reduce: last of 8 chunk-blocks for this m-tile sums ----
    __threadfence();
    __syncthreads();
    if (tid == 0) {
        const int old = atomicAdd(&g_cnt[mt], 1);
        s_last = (old == KSPLIT - 1) ? 1 : 0;
    }
    __syncthreads();

    if (s_last) {
        __threadfence();
        const int o4 = (tid & 15) * 4;
        const int br = tid >> 4;        // 0..15
        #pragma unroll
        for (int p = 0; p < 2; ++p) {
            const int bl = br + p * 16;
            const int b  = b0 + bl;
            float4 v = make_float4(0.f, 0.f, 0.f, 0.f);
            #pragma unroll
            for (int kk = 0; kk < KSPLIT; ++kk) {
                const float4 q = *(const float4*)
                    &g_Part[((kk << 11) + b) * OUT_DIM + o4];
                v.x += q.x; v.y += q.y; v.z += q.z; v.w += q.w;
            }
            if (b < batch)
                *(float4*)&out[b * OUT_DIM + o4] = v;
        }
        if (tid == 0) g_cnt[mt] = 0;    // self-reset for graph replay
    }
}

extern "C" void kernel_launch(void* const* d_in, const int* in_sizes, int n_in,
                              void* d_out, int out_size)
{
    const float* inp   = (const float*)d_in[0];   // (batch, 64)
    const float* gridp = (const float*)d_in[1];   // (4096, 6)
    const float* coefp = (const float*)d_in[2];   // (4096, 8)
    const float* sbase = (const float*)d_in[3];   // (4096,)
    const float* ssp   = (const float*)d_in[4];   // (4096,)
    const float* maskp = (const float*)d_in[5];   // (4096,)
    float* out = (float*)d_out;                   // (batch, 64)

    int batch = in_sizes[0] / IN_DIM;
    if (batch > MAXB) batch = MAXB;

    kan_c2t<<<(KSPLIT * KCHUNK * OUT_DIM + 255) / 256, 256>>>
        (coefp, sbase, ssp, maskp);

    const int mtiles = (batch + MTILE - 1) / MTILE;   // 64
    dim3 ggrid(mtiles, KSPLIT);                       // 64 x 8 = 512 blocks
    kan_gemm<<<ggrid, 256>>>(inp, gridp, out, batch);
}